// round 16
// baseline (speedup 1.0000x reference)
#include <cuda_runtime.h>
#include <cuda_fp16.h>
#include <cstdint>

// ---------------- scratch ----------------
__device__ __align__(1024) __half g_bhalf[557056];  // [17 slots][512 k][64 n] fp16 (slot16 = wq, cols 0-15)
__device__ float g_Z[512];                          // [b][n]

// ---------------- helpers ----------------
__device__ __forceinline__ uint32_t smem_u32(const void* p) {
    uint32_t a; asm("{ .reg .u64 t; cvta.to.shared.u64 t, %1; cvt.u32.u64 %0, t; }" : "=r"(a) : "l"(p));
    return a;
}
__device__ __forceinline__ uint32_t h2u(__half2 h) { return *reinterpret_cast<uint32_t*>(&h); }
__device__ __forceinline__ float tanh_fast(float x) {
    float e; asm("ex2.approx.f32 %0, %1;" : "=f"(e) : "f"(x * 2.885390082f));
    float r; asm("rcp.approx.f32 %0, %1;" : "=f"(r) : "f"(e + 1.0f));
    return fmaf(-2.0f, r, 1.0f);
}
__device__ __forceinline__ float exp_fast(float x) {
    float e; asm("ex2.approx.f32 %0, %1;" : "=f"(e) : "f"(x * 1.44269504f));
    return e;
}
#define CPASYNC16(dst, src) asm volatile( \
    "cp.async.cg.shared.global [%0], [%1], 16;" :: "r"(dst), "l"(src) : "memory")
#define CPCOMMIT() asm volatile("cp.async.commit_group;" ::: "memory")
#define CPWAIT2()  asm volatile("cp.async.wait_group 2;" ::: "memory")
#define BARSYNC(id)   asm volatile("bar.sync %0, 256;" :: "r"(id) : "memory")
#define BAR_ARRIVE4() asm volatile("bar.arrive 4, 512;" ::: "memory")
#define BAR_SYNC4()   asm volatile("bar.sync 4, 512;" ::: "memory")

__device__ __forceinline__ void ldsm4(uint32_t* r, uint32_t a) {
    asm volatile("ldmatrix.sync.aligned.m8n8.x4.shared.b16 {%0,%1,%2,%3}, [%4];"
        : "=r"(r[0]), "=r"(r[1]), "=r"(r[2]), "=r"(r[3]) : "r"(a));
}
__device__ __forceinline__ void ldsm4t(uint32_t* r, uint32_t a) {
    asm volatile("ldmatrix.sync.aligned.m8n8.x4.trans.shared.b16 {%0,%1,%2,%3}, [%4];"
        : "=r"(r[0]), "=r"(r[1]), "=r"(r[2]), "=r"(r[3]) : "r"(a));
}
__device__ __forceinline__ void mma16816(float* d, const uint32_t* a, uint32_t b0, uint32_t b1) {
    asm volatile("mma.sync.aligned.m16n8k16.row.col.f32.f16.f16.f32 "
        "{%0,%1,%2,%3}, {%4,%5,%6,%7}, {%8,%9}, {%0,%1,%2,%3};"
        : "+f"(d[0]), "+f"(d[1]), "+f"(d[2]), "+f"(d[3])
        : "r"(a[0]), "r"(a[1]), "r"(a[2]), "r"(a[3]), "r"(b0), "r"(b1));
}

// ---------------- kP1: zero out + g_Z ----------------
__global__ void kP1(float* __restrict__ out) {
    int id = blockIdx.x * 256 + threadIdx.x;      // 33280
    if (id < 32768) out[id] = 0.f;
    else if (id < 33280) g_Z[id - 32768] = 0.f;
}

// ---------------- kP2: W_v -> fp16 [16][512][64] ----------------
__global__ void kP2(const float* __restrict__ Wv) {
    int id = blockIdx.x * 256 + threadIdx.x;      // 524288
    int h = id >> 15, k = (id >> 6) & 511, n = id & 63;
    g_bhalf[id] = __float2half_rn(Wv[(size_t)k * 1024 + h * 64 + n]);
}

// ---------------- kP3: slot16 = wq (computed inline), cols 16-63 zero ----------------
__global__ void kP3(const float* __restrict__ Wk, const float* __restrict__ q) {
    int id = blockIdx.x * 256 + threadIdx.x;      // 32768
    int k = id >> 6, n = id & 63;
    float a = 0.f;
    if (n < 16) {
        #pragma unroll 8
        for (int kk = 0; kk < 64; kk++) a += Wk[(size_t)k * 1024 + n * 64 + kk] * q[n * 64 + kk];
    }
    g_bhalf[524288 + id] = __float2half_rn(a);
}

// ---------------- k3: R9 config + pseudo-slot MMA pruning ----------------
// smem: A 0..133120 (128x1040B), B 133120..206848 (2 groups x 4 stages x 9216),
// Y 206848..224256 (128x136B fp16), bias16 224256..226304, sred 226304..227328,
// sdot16 227328..231424, sZ 231424..231488
#define SM_A    0
#define SM_B    133120
#define SM_BST  9216
#define SM_Y    206848
#define YSTR    136
#define SM_BIAS 224256
#define SM_RED  226304
#define SM_DOT  227328
#define SM_Z    231424
#define K3_DYN  231488
#define ASTR    1040
#define BSTR    144

__global__ __launch_bounds__(512, 1) void k3(const float* __restrict__ x,
                                             const float* __restrict__ bv,
                                             float* __restrict__ out) {
    extern __shared__ char sm[];
    uint32_t sb = smem_u32(sm);
    int t = threadIdx.x, wid = t >> 5, l = t & 31;
    int g = wid >> 3, w8 = wid & 7, rb = w8 & 3, cb = w8 >> 2;
    int u = t & 255;
    int blk = blockIdx.x, b = blk >> 5, st = blk & 31;
    __half* sbias16 = (__half*)(sm + SM_BIAS);
    float*  sred    = (float*)(sm + SM_RED);
    __half* sdot16  = (__half*)(sm + SM_DOT);
    float*  sZf     = (float*)(sm + SM_Z);
    const char* bbase = (const char*)g_bhalf;
    int br = u >> 2, bq = u & 3;    // B loader: row 0..63, 32B quarter

    // B prologue: stages 0,1 (pseudo slot16, chunks 0,1)
    #pragma unroll
    for (int c = 0; c < 2; c++) {
        const char* s = bbase + ((size_t)(16 * 512 + g * 256 + c * 64 + br) * 64) * 2 + bq * 32;
        uint32_t d = sb + SM_B + (g * 4 + c) * SM_BST + br * BSTR + bq * 32;
        CPASYNC16(d, s); CPASYNC16(d + 16, s + 16);
        CPCOMMIT();
    }

    // A tile: 128 rows fp32 -> fp16 (each thread: one 128-float quarter-row)
    {
        int r = t >> 2, q = t & 3;
        const float4* xr = (const float4*)(x + (size_t)(b * 4096 + st * 128 + r) * 512 + q * 128);
        char* arow = sm + SM_A + r * ASTR + q * 256;
        #pragma unroll 8
        for (int i = 0; i < 16; i++) {
            float4 f0 = xr[2 * i], f1 = xr[2 * i + 1];
            uint4 v;
            v.x = h2u(__floats2half2_rn(f0.x, f0.y));
            v.y = h2u(__floats2half2_rn(f0.z, f0.w));
            v.z = h2u(__floats2half2_rn(f1.x, f1.y));
            v.w = h2u(__floats2half2_rn(f1.z, f1.w));
            *(uint4*)(arow + i * 16) = v;
        }
    }
    for (int i = t; i < 1024; i += 512) sbias16[i] = __float2half_rn(bv[i]);
    if (t < 16) sZf[t] = 0.f;

    uint32_t a_base = sb + SM_A + (rb * 32 + (l & 7) + 8 * ((l >> 3) & 1)) * ASTR
                    + (l >> 4) * 16 + g * 512;
    uint32_t b_lane = ((l & 7) + 8 * ((l >> 3) & 1)) * BSTR + (cb * 32 + 8 * (l >> 4)) * 2;
    int stag = (w8 & 1) << 1;       // kk stagger: odd warps rotate by 2
    float acc[2][4][4];

    for (int it = 0; it < 68; it++) {
        int ip = it + 2;
        if (ip < 68) {              // prefetch stage (ip&3): last read at iter ip-4, safe
            int slot = (ip < 4) ? 16 : ((ip - 4) >> 2);
            int ck = ip & 3;
            const char* s = bbase + ((size_t)(slot * 512 + g * 256 + ck * 64 + br) * 64) * 2 + bq * 32;
            uint32_t d = sb + SM_B + (g * 4 + ck) * SM_BST + br * BSTR + bq * 32;
            CPASYNC16(d, s); CPASYNC16(d + 16, s + 16);
        }
        CPCOMMIT();
        CPWAIT2();
        if (it == 0) __syncthreads();   // A + bias visible CTA-wide; stage0 ready
        else BARSYNC(1 + g);            // group's stage (it&3) ready

        uint32_t bbuf = sb + SM_B + (g * 4 + (it & 3)) * SM_BST;
        uint32_t aoff = (it & 3) * 128;
        bool ps = (it < 4);             // pseudo slot: only cols 0-15 are non-zero
        if ((it & 3) == 0) {
            #pragma unroll
            for (int m = 0; m < 2; m++)
                #pragma unroll
                for (int n = 0; n < 4; n++)
                    #pragma unroll
                    for (int e = 0; e < 4; e++) acc[m][n][e] = 0.f;
        }
        if (!ps || cb == 0) {
            #pragma unroll
            for (int kk = 0; kk < 4; kk++) {
                int kks = (kk + stag) & 3;
                uint32_t a0[4], a1[4], bf0[4], bf1[4];
                uint32_t ko = aoff + kks * 32;
                ldsm4(a0, a_base + ko);
                ldsm4(a1, a_base + 16 * ASTR + ko);
                uint32_t brow = bbuf + b_lane + kks * 16 * BSTR;
                ldsm4t(bf0, brow);
                #pragma unroll
                for (int n = 0; n < 2; n++) {
                    mma16816(acc[0][n], a0, bf0[2 * n], bf0[2 * n + 1]);
                    mma16816(acc[1][n], a1, bf0[2 * n], bf0[2 * n + 1]);
                }
                if (!ps) {              // pseudo: cols 16-31 of cb==0 are zero too
                    ldsm4t(bf1, brow + 32);
                    #pragma unroll
                    for (int n = 0; n < 2; n++) {
                        mma16816(acc[0][n + 2], a0, bf1[2 * n], bf1[2 * n + 1]);
                        mma16816(acc[1][n + 2], a1, bf1[2 * n], bf1[2 * n + 1]);
                    }
                }
            }
        }

        if ((it & 3) == 3) {            // slot complete
            int hIdx = (it >> 2) - 1;   // -1 = pseudo (dot)
            int owner = (hIdx < 0) ? 0 : (1 - (hIdx & 1));
            if (g != owner) {
                // dumper: write partial-y fp16, non-blocking arrive
                #pragma unroll
                for (int m = 0; m < 2; m++) {
                    int rA = rb * 32 + 16 * m + (l >> 2);
                    #pragma unroll
                    for (int n = 0; n < 4; n++) {
                        int c0 = cb * 32 + 8 * n + 2 * (l & 3);
                        *(uint32_t*)(sm + SM_Y + rA * YSTR + c0 * 2) =
                            h2u(__floats2half2_rn(acc[m][n][0], acc[m][n][1]));
                        *(uint32_t*)(sm + SM_Y + (rA + 8) * YSTR + c0 * 2) =
                            h2u(__floats2half2_rn(acc[m][n][2], acc[m][n][3]));
                    }
                }
                BAR_ARRIVE4();
            } else {
                BAR_SYNC4();
                if (hIdx < 0) {
                    if (w8 < 4) {        // cols 0..15 hold the dot
                        #pragma unroll
                        for (int m = 0; m < 2; m++) {
                            int rA = rb * 32 + 16 * m + (l >> 2);
                            #pragma unroll
                            for (int n = 0; n < 2; n++) {
                                int c0 = 8 * n + 2 * (l & 3);
                                float2 fA = __half22float2(*(const __half2*)(sm + SM_Y + rA * YSTR + c0 * 2));
                                float2 fB = __half22float2(*(const __half2*)(sm + SM_Y + (rA + 8) * YSTR + c0 * 2));
                                __half h0 = __float2half_rn(exp_fast(acc[m][n][0] + fA.x));
                                __half h1 = __float2half_rn(exp_fast(acc[m][n][1] + fA.y));
                                __half h2 = __float2half_rn(exp_fast(acc[m][n][2] + fB.x));
                                __half h3 = __float2half_rn(exp_fast(acc[m][n][3] + fB.y));
                                sdot16[rA * 16 + c0]           = h0;
                                sdot16[rA * 16 + c0 + 1]       = h1;
                                sdot16[(rA + 8) * 16 + c0]     = h2;
                                sdot16[(rA + 8) * 16 + c0 + 1] = h3;
                                atomicAdd(&sZf[c0],     __half2float(h0) + __half2float(h2));
                                atomicAdd(&sZf[c0 + 1], __half2float(h1) + __half2float(h3));
                            }
                        }
                    }
                } else {
                    float s0[4], s1[4];
                    #pragma unroll
                    for (int n = 0; n < 4; n++) { s0[n] = 0.f; s1[n] = 0.f; }
                    #pragma unroll
                    for (int m = 0; m < 2; m++) {
                        int rA = rb * 32 + 16 * m + (l >> 2);
                        float wA = __half2float(sdot16[rA * 16 + hIdx]);
                        float wB = __half2float(sdot16[(rA + 8) * 16 + hIdx]);
                        #pragma unroll
                        for (int n = 0; n < 4; n++) {
                            int c0 = cb * 32 + 8 * n + 2 * (l & 3);
                            float2 fA = __half22float2(*(const __half2*)(sm + SM_Y + rA * YSTR + c0 * 2));
                            float2 fB = __half22float2(*(const __half2*)(sm + SM_Y + (rA + 8) * YSTR + c0 * 2));
                            float2 bf = __half22float2(*(const __half2*)(sbias16 + hIdx * 64 + c0));
                            s0[n] += wA * tanh_fast(acc[m][n][0] + fA.x + bf.x)
                                   + wB * tanh_fast(acc[m][n][2] + fB.x + bf.x);
                            s1[n] += wA * tanh_fast(acc[m][n][1] + fA.y + bf.y)
                                   + wB * tanh_fast(acc[m][n][3] + fB.y + bf.y);
                        }
                    }
                    #pragma unroll
                    for (int o = 4; o < 32; o <<= 1)
                        #pragma unroll
                        for (int n = 0; n < 4; n++) {
                            s0[n] += __shfl_xor_sync(~0u, s0[n], o);
                            s1[n] += __shfl_xor_sync(~0u, s1[n], o);
                        }
                    if (l < 4) {
                        #pragma unroll
                        for (int n = 0; n < 4; n++) {
                            sred[w8 * 32 + 8 * n + 2 * l]     = s0[n];
                            sred[w8 * 32 + 8 * n + 2 * l + 1] = s1[n];
                        }
                    }
                    BARSYNC(5 + g);
                    if (u < 64) {
                        int cw = u >> 5, cc = u & 31;
                        float s = sred[(cw * 4 + 0) * 32 + cc] + sred[(cw * 4 + 1) * 32 + cc]
                                + sred[(cw * 4 + 2) * 32 + cc] + sred[(cw * 4 + 3) * 32 + cc];
                        atomicAdd(&out[b * 1024 + hIdx * 64 + u], s);
                    }
                }
            }
        }
    }
    __syncthreads();
    if (t < 16) atomicAdd(&g_Z[b * 16 + t], sZf[t]);
}

// ---------------- k4: normalize ----------------
__global__ void k4(float* __restrict__ out) {
    int id = blockIdx.x * 256 + threadIdx.x;
    out[id] = out[id] / g_Z[id >> 6];
}

// ---------------- launch ----------------
extern "C" void kernel_launch(void* const* d_in, const int* in_sizes, int n_in,
                              void* d_out, int out_size) {
    const float* kv = (const float*)d_in[0];
    const float* Wk = (const float*)d_in[1];
    const float* Wv = (const float*)d_in[3];
    const float* bv = (const float*)d_in[4];
    const float* q  = (const float*)d_in[5];
    float* out = (float*)d_out;
    cudaFuncSetAttribute(k3, cudaFuncAttributeMaxDynamicSharedMemorySize, K3_DYN);
    kP1<<<130, 256>>>(out);
    kP2<<<2048, 256>>>(Wv);
    kP3<<<128, 256>>>(Wk, q);
    k3<<<1024, 512, K3_DYN>>>(kv, bv, out);
    k4<<<128, 256>>>(out);
}

// round 17
// speedup vs baseline: 1.0701x; 1.0701x over previous
#include <cuda_runtime.h>
#include <cuda_fp16.h>
#include <cstdint>

// ---------------- scratch ----------------
__device__ __align__(1024) __half g_bhalf[557056];  // [17 slots][512 k][64 n] fp16 (slot16 = wq cols 0-15)
__device__ float g_Z[512];                          // [b][n]

// ---------------- helpers ----------------
__device__ __forceinline__ uint32_t smem_u32(const void* p) {
    uint32_t a; asm("{ .reg .u64 t; cvta.to.shared.u64 t, %1; cvt.u32.u64 %0, t; }" : "=r"(a) : "l"(p));
    return a;
}
__device__ __forceinline__ uint32_t h2u(__half2 h) { return *reinterpret_cast<uint32_t*>(&h); }
__device__ __forceinline__ float tanh_fast(float x) {
    float e; asm("ex2.approx.f32 %0, %1;" : "=f"(e) : "f"(x * 2.885390082f));
    float r; asm("rcp.approx.f32 %0, %1;" : "=f"(r) : "f"(e + 1.0f));
    return fmaf(-2.0f, r, 1.0f);
}
__device__ __forceinline__ float exp_fast(float x) {
    float e; asm("ex2.approx.f32 %0, %1;" : "=f"(e) : "f"(x * 1.44269504f));
    return e;
}
#define CPASYNC16(dst, src) asm volatile( \
    "cp.async.cg.shared.global [%0], [%1], 16;" :: "r"(dst), "l"(src) : "memory")
#define CPCOMMIT() asm volatile("cp.async.commit_group;" ::: "memory")
#define CPWAIT2()  asm volatile("cp.async.wait_group 2;" ::: "memory")
#define BARSYNC(id)   asm volatile("bar.sync %0, 256;" :: "r"(id) : "memory")
#define BAR_ARRIVE4() asm volatile("bar.arrive 4, 512;" ::: "memory")
#define BAR_SYNC4()   asm volatile("bar.sync 4, 512;" ::: "memory")

__device__ __forceinline__ void ldsm4(uint32_t* r, uint32_t a) {
    asm volatile("ldmatrix.sync.aligned.m8n8.x4.shared.b16 {%0,%1,%2,%3}, [%4];"
        : "=r"(r[0]), "=r"(r[1]), "=r"(r[2]), "=r"(r[3]) : "r"(a));
}
__device__ __forceinline__ void ldsm4t(uint32_t* r, uint32_t a) {
    asm volatile("ldmatrix.sync.aligned.m8n8.x4.trans.shared.b16 {%0,%1,%2,%3}, [%4];"
        : "=r"(r[0]), "=r"(r[1]), "=r"(r[2]), "=r"(r[3]) : "r"(a));
}
__device__ __forceinline__ void mma16816(float* d, const uint32_t* a, uint32_t b0, uint32_t b1) {
    asm volatile("mma.sync.aligned.m16n8k16.row.col.f32.f16.f16.f32 "
        "{%0,%1,%2,%3}, {%4,%5,%6,%7}, {%8,%9}, {%0,%1,%2,%3};"
        : "+f"(d[0]), "+f"(d[1]), "+f"(d[2]), "+f"(d[3])
        : "r"(a[0]), "r"(a[1]), "r"(a[2]), "r"(a[3]), "r"(b0), "r"(b1));
}

// ---------------- kPrep: one launch, three independent jobs ----------------
// blk [0, 2048):      W_v -> fp16 slots 0-15
// blk [2048, 2176):   slot 16 = wq (inline-computed), cols 16-63 zero
// blk [2176, 2306):   zero out + g_Z
__global__ void kPrep(const float* __restrict__ Wv, const float* __restrict__ Wk,
                      const float* __restrict__ q, float* __restrict__ out) {
    int blk = blockIdx.x, t = threadIdx.x;
    if (blk < 2048) {
        int id = blk * 256 + t;                   // 524288
        int h = id >> 15, k = (id >> 6) & 511, n = id & 63;
        g_bhalf[id] = __float2half_rn(Wv[(size_t)k * 1024 + h * 64 + n]);
    } else if (blk < 2176) {
        int id = (blk - 2048) * 256 + t;          // 32768
        int k = id >> 6, n = id & 63;
        float a = 0.f;
        if (n < 16) {
            #pragma unroll 8
            for (int kk = 0; kk < 64; kk++)
                a += Wk[(size_t)k * 1024 + n * 64 + kk] * q[n * 64 + kk];
        }
        g_bhalf[524288 + id] = __float2half_rn(a);
    } else {
        int id = (blk - 2176) * 256 + t;          // 33280
        if (id < 32768) out[id] = 0.f;
        else if (id < 33280) g_Z[id - 32768] = 0.f;
    }
}

// ---------------- k3: R9 verbatim — 128-row tiles, 16 warps, 2-way K-split, 4-stage rings ----------------
// smem: A 0..133120 (128x1040B), B 133120..206848 (2 groups x 4 stages x 9216),
// Y 206848..224256 (128x136B fp16), bias16 224256..226304, sred 226304..227328,
// sdot16 227328..231424, sZ 231424..231488
#define SM_A    0
#define SM_B    133120
#define SM_BST  9216
#define SM_Y    206848
#define YSTR    136
#define SM_BIAS 224256
#define SM_RED  226304
#define SM_DOT  227328
#define SM_Z    231424
#define K3_DYN  231488
#define ASTR    1040
#define BSTR    144

__global__ __launch_bounds__(512, 1) void k3(const float* __restrict__ x,
                                             const float* __restrict__ bv,
                                             float* __restrict__ out) {
    extern __shared__ char sm[];
    uint32_t sb = smem_u32(sm);
    int t = threadIdx.x, wid = t >> 5, l = t & 31;
    int g = wid >> 3, w8 = wid & 7, rb = w8 & 3, cb = w8 >> 2;
    int u = t & 255;
    int blk = blockIdx.x, b = blk >> 5, st = blk & 31;
    __half* sbias16 = (__half*)(sm + SM_BIAS);
    float*  sred    = (float*)(sm + SM_RED);
    __half* sdot16  = (__half*)(sm + SM_DOT);
    float*  sZf     = (float*)(sm + SM_Z);
    const char* bbase = (const char*)g_bhalf;
    int br = u >> 2, bq = u & 3;    // B loader: row 0..63, 32B quarter

    // B prologue: stages 0,1 (pseudo slot16, chunks 0,1), one commit each
    #pragma unroll
    for (int c = 0; c < 2; c++) {
        const char* s = bbase + ((size_t)(16 * 512 + g * 256 + c * 64 + br) * 64) * 2 + bq * 32;
        uint32_t d = sb + SM_B + (g * 4 + c) * SM_BST + br * BSTR + bq * 32;
        CPASYNC16(d, s); CPASYNC16(d + 16, s + 16);
        CPCOMMIT();
    }

    // A tile: 128 rows fp32 -> fp16 (each thread: one 128-float quarter-row)
    {
        int r = t >> 2, q = t & 3;
        const float4* xr = (const float4*)(x + (size_t)(b * 4096 + st * 128 + r) * 512 + q * 128);
        char* arow = sm + SM_A + r * ASTR + q * 256;
        #pragma unroll 8
        for (int i = 0; i < 16; i++) {
            float4 f0 = xr[2 * i], f1 = xr[2 * i + 1];
            uint4 v;
            v.x = h2u(__floats2half2_rn(f0.x, f0.y));
            v.y = h2u(__floats2half2_rn(f0.z, f0.w));
            v.z = h2u(__floats2half2_rn(f1.x, f1.y));
            v.w = h2u(__floats2half2_rn(f1.z, f1.w));
            *(uint4*)(arow + i * 16) = v;
        }
    }
    for (int i = t; i < 1024; i += 512) sbias16[i] = __float2half_rn(bv[i]);
    if (t < 16) sZf[t] = 0.f;

    uint32_t a_base = sb + SM_A + (rb * 32 + (l & 7) + 8 * ((l >> 3) & 1)) * ASTR
                    + (l >> 4) * 16 + g * 512;
    uint32_t b_lane = ((l & 7) + 8 * ((l >> 3) & 1)) * BSTR + (cb * 32 + 8 * (l >> 4)) * 2;
    int stag = (w8 & 1) << 1;       // kk stagger: odd warps rotate by 2
    float acc[2][4][4];

    for (int it = 0; it < 68; it++) {
        int ip = it + 2;
        if (ip < 68) {              // prefetch stage (ip&3): last read at iter ip-4, safe
            int slot = (ip < 4) ? 16 : ((ip - 4) >> 2);
            int ck = ip & 3;
            const char* s = bbase + ((size_t)(slot * 512 + g * 256 + ck * 64 + br) * 64) * 2 + bq * 32;
            uint32_t d = sb + SM_B + (g * 4 + ck) * SM_BST + br * BSTR + bq * 32;
            CPASYNC16(d, s); CPASYNC16(d + 16, s + 16);
        }
        CPCOMMIT();
        CPWAIT2();
        if (it == 0) __syncthreads();   // A + bias visible CTA-wide; stage0 ready
        else BARSYNC(1 + g);            // group's stage (it&3) ready

        uint32_t bbuf = sb + SM_B + (g * 4 + (it & 3)) * SM_BST;
        uint32_t aoff = (it & 3) * 128;
        if ((it & 3) == 0) {
            #pragma unroll
            for (int m = 0; m < 2; m++)
                #pragma unroll
                for (int n = 0; n < 4; n++)
                    #pragma unroll
                    for (int e = 0; e < 4; e++) acc[m][n][e] = 0.f;
        }
        #pragma unroll
        for (int kk = 0; kk < 4; kk++) {
            int kks = (kk + stag) & 3;
            uint32_t a0[4], a1[4], bf0[4], bf1[4];
            uint32_t ko = aoff + kks * 32;
            ldsm4(a0, a_base + ko);
            ldsm4(a1, a_base + 16 * ASTR + ko);
            uint32_t brow = bbuf + b_lane + kks * 16 * BSTR;
            ldsm4t(bf0, brow);
            ldsm4t(bf1, brow + 32);
            #pragma unroll
            for (int n = 0; n < 2; n++) {
                mma16816(acc[0][n],     a0, bf0[2 * n], bf0[2 * n + 1]);
                mma16816(acc[1][n],     a1, bf0[2 * n], bf0[2 * n + 1]);
                mma16816(acc[0][n + 2], a0, bf1[2 * n], bf1[2 * n + 1]);
                mma16816(acc[1][n + 2], a1, bf1[2 * n], bf1[2 * n + 1]);
            }
        }

        if ((it & 3) == 3) {            // slot complete
            int hIdx = (it >> 2) - 1;   // -1 = pseudo (dot)
            int owner = (hIdx < 0) ? 0 : (1 - (hIdx & 1));
            if (g != owner) {
                // dumper: write partial-y fp16, non-blocking arrive
                #pragma unroll
                for (int m = 0; m < 2; m++) {
                    int rA = rb * 32 + 16 * m + (l >> 2);
                    #pragma unroll
                    for (int n = 0; n < 4; n++) {
                        int c0 = cb * 32 + 8 * n + 2 * (l & 3);
                        *(uint32_t*)(sm + SM_Y + rA * YSTR + c0 * 2) =
                            h2u(__floats2half2_rn(acc[m][n][0], acc[m][n][1]));
                        *(uint32_t*)(sm + SM_Y + (rA + 8) * YSTR + c0 * 2) =
                            h2u(__floats2half2_rn(acc[m][n][2], acc[m][n][3]));
                    }
                }
                BAR_ARRIVE4();
            } else {
                BAR_SYNC4();
                if (hIdx < 0) {
                    if (w8 < 4) {        // cols 0..15 hold the dot
                        #pragma unroll
                        for (int m = 0; m < 2; m++) {
                            int rA = rb * 32 + 16 * m + (l >> 2);
                            #pragma unroll
                            for (int n = 0; n < 2; n++) {
                                int c0 = 8 * n + 2 * (l & 3);
                                float2 fA = __half22float2(*(const __half2*)(sm + SM_Y + rA * YSTR + c0 * 2));
                                float2 fB = __half22float2(*(const __half2*)(sm + SM_Y + (rA + 8) * YSTR + c0 * 2));
                                __half h0 = __float2half_rn(exp_fast(acc[m][n][0] + fA.x));
                                __half h1 = __float2half_rn(exp_fast(acc[m][n][1] + fA.y));
                                __half h2 = __float2half_rn(exp_fast(acc[m][n][2] + fB.x));
                                __half h3 = __float2half_rn(exp_fast(acc[m][n][3] + fB.y));
                                sdot16[rA * 16 + c0]           = h0;
                                sdot16[rA * 16 + c0 + 1]       = h1;
                                sdot16[(rA + 8) * 16 + c0]     = h2;
                                sdot16[(rA + 8) * 16 + c0 + 1] = h3;
                                atomicAdd(&sZf[c0],     __half2float(h0) + __half2float(h2));
                                atomicAdd(&sZf[c0 + 1], __half2float(h1) + __half2float(h3));
                            }
                        }
                    }
                } else {
                    float s0[4], s1[4];
                    #pragma unroll
                    for (int n = 0; n < 4; n++) { s0[n] = 0.f; s1[n] = 0.f; }
                    #pragma unroll
                    for (int m = 0; m < 2; m++) {
                        int rA = rb * 32 + 16 * m + (l >> 2);
                        float wA = __half2float(sdot16[rA * 16 + hIdx]);
                        float wB = __half2float(sdot16[(rA + 8) * 16 + hIdx]);
                        #pragma unroll
                        for (int n = 0; n < 4; n++) {
                            int c0 = cb * 32 + 8 * n + 2 * (l & 3);
                            float2 fA = __half22float2(*(const __half2*)(sm + SM_Y + rA * YSTR + c0 * 2));
                            float2 fB = __half22float2(*(const __half2*)(sm + SM_Y + (rA + 8) * YSTR + c0 * 2));
                            float2 bf = __half22float2(*(const __half2*)(sbias16 + hIdx * 64 + c0));
                            s0[n] += wA * tanh_fast(acc[m][n][0] + fA.x + bf.x)
                                   + wB * tanh_fast(acc[m][n][2] + fB.x + bf.x);
                            s1[n] += wA * tanh_fast(acc[m][n][1] + fA.y + bf.y)
                                   + wB * tanh_fast(acc[m][n][3] + fB.y + bf.y);
                        }
                    }
                    #pragma unroll
                    for (int o = 4; o < 32; o <<= 1)
                        #pragma unroll
                        for (int n = 0; n < 4; n++) {
                            s0[n] += __shfl_xor_sync(~0u, s0[n], o);
                            s1[n] += __shfl_xor_sync(~0u, s1[n], o);
                        }
                    if (l < 4) {
                        #pragma unroll
                        for (int n = 0; n < 4; n++) {
                            sred[w8 * 32 + 8 * n + 2 * l]     = s0[n];
                            sred[w8 * 32 + 8 * n + 2 * l + 1] = s1[n];
                        }
                    }
                    BARSYNC(5 + g);
                    if (u < 64) {
                        int cw = u >> 5, cc = u & 31;
                        float s = sred[(cw * 4 + 0) * 32 + cc] + sred[(cw * 4 + 1) * 32 + cc]
                                + sred[(cw * 4 + 2) * 32 + cc] + sred[(cw * 4 + 3) * 32 + cc];
                        atomicAdd(&out[b * 1024 + hIdx * 64 + u], s);
                    }
                }
            }
        }
    }
    __syncthreads();
    if (t < 16) atomicAdd(&g_Z[b * 16 + t], sZf[t]);
}

// ---------------- k4: normalize ----------------
__global__ void k4(float* __restrict__ out) {
    int id = blockIdx.x * 256 + threadIdx.x;
    out[id] = out[id] / g_Z[id >> 6];
}

// ---------------- launch ----------------
extern "C" void kernel_launch(void* const* d_in, const int* in_sizes, int n_in,
                              void* d_out, int out_size) {
    const float* kv = (const float*)d_in[0];
    const float* Wk = (const float*)d_in[1];
    const float* Wv = (const float*)d_in[3];
    const float* bv = (const float*)d_in[4];
    const float* q  = (const float*)d_in[5];
    float* out = (float*)d_out;
    cudaFuncSetAttribute(k3, cudaFuncAttributeMaxDynamicSharedMemorySize, K3_DYN);
    kPrep<<<2306, 256>>>(Wv, Wk, q, out);
    k3<<<1024, 512, K3_DYN>>>(kv, bv, out);
    k4<<<128, 256>>>(out);
}